// round 16
// baseline (speedup 1.0000x reference)
#include <cuda_runtime.h>
#include <stdint.h>

#define N_NODES 10242
#define NNZ_MAX 71694
#define BT      32          // B*T
#define C_IN    16
#define F       512         // C_IN * BT
#define KS      20
#define COUT    32
#define CK      (C_IN * KS)
#define NSLOT   5           // rolling window (105MB) -> nk=4 proj passes
#define SORT_BLOCKS 41      // 41*256 >= 10242
#define XP_BLOCKS   ((N_NODES + 7) / 8)
#define WARP_BLOCKS ((N_NODES * 32 + 255) / 256)   // 1281

typedef unsigned long long ull;

// ---------------- device scratch (no runtime allocation allowed) ----------------
__device__ float g_buf[(size_t)NSLOT * N_NODES * F];   // rolling 5-slice window
__device__ int   g_rowptr[N_NODES + 1];
__device__ int   g_cursor[N_NODES];
__device__ int   g_colidx[NNZ_MAX];
__device__ float g_vals[NNZ_MAX];
__device__ float g_Wre[KS * C_IN * COUT];          // [k][c][cout] = W[cout*CK + c*KS + k]  (40KB)

// ---------------- kernel A: count+scan+W-reshape (single block) ----------------
__global__ void __launch_bounds__(1024) prep_kernel(const int* __restrict__ erow,
                                                    const float* __restrict__ W,
                                                    int nnz) {
    __shared__ int scnt[N_NODES];
    __shared__ int ssum[1024];
    int t = threadIdx.x;

    for (int i = t; i < N_NODES; i += 1024) scnt[i] = 0;
    __syncthreads();
    for (int e = t; e < nnz; e += 1024) atomicAdd(&scnt[erow[e]], 1);
    __syncthreads();

    const int CH = 11;                 // 1024*11 >= 10242
    int base = t * CH;
    int s = 0;
#pragma unroll
    for (int i = 0; i < CH; ++i) {
        int idx = base + i;
        if (idx < N_NODES) s += scnt[idx];
    }
    ssum[t] = s;
    __syncthreads();
    for (int off = 1; off < 1024; off <<= 1) {
        int v = (t >= off) ? ssum[t - off] : 0;
        __syncthreads();
        ssum[t] += v;
        __syncthreads();
    }
    int run = ssum[t] - s;
#pragma unroll
    for (int i = 0; i < CH; ++i) {
        int idx = base + i;
        if (idx < N_NODES) {
            g_rowptr[idx] = run;
            g_cursor[idx] = run;
            run += scnt[idx];
        }
    }
    if (t == 0) g_rowptr[N_NODES] = nnz;

    // W reshape: g_Wre[k*512 + c*32 + cout] = W[cout*CK + c*KS + k]
    for (int i = t; i < KS * C_IN * COUT; i += 1024) {
        int k = i >> 9;
        int r = i & 511;
        int c = r >> 5;
        int cout = r & 31;
        g_Wre[i] = W[cout * CK + c * KS + k];
    }
}

// ---------------- kernel B: scatter ----------------
__global__ void csr_scatter_kernel(const int* __restrict__ erow,
                                   const int* __restrict__ ecol,
                                   const float* __restrict__ eval, int nnz) {
    int e = blockIdx.x * blockDim.x + threadIdx.x;
    if (e < nnz) {
        int r = erow[e];
        int p = atomicAdd(&g_cursor[r], 1);
        g_colidx[p] = ecol[e];
        g_vals[p]   = eval[e];
    }
}

// ---------------- kernel C: per-row sort + transpose slice 0 (split grid) ----------------
__global__ void __launch_bounds__(256) sort_xpose_kernel(const float* __restrict__ x) {
    if (blockIdx.x < SORT_BLOCKS) {
        // canonical per-row order (col asc, then val asc) -> deterministic fp sums
        int r = blockIdx.x * 256 + threadIdx.x;
        if (r >= N_NODES) return;
        int s = g_rowptr[r], e = g_rowptr[r + 1];
        for (int i = s + 1; i < e; ++i) {
            int   kc = g_colidx[i];
            float kv = g_vals[i];
            int j = i - 1;
            while (j >= s && (g_colidx[j] > kc || (g_colidx[j] == kc && g_vals[j] > kv))) {
                g_colidx[j + 1] = g_colidx[j];
                g_vals[j + 1]   = g_vals[j];
                --j;
            }
            g_colidx[j + 1] = kc;
            g_vals[j + 1]   = kv;
        }
        return;
    }
    // transpose: x[bt=lane, n, c] -> g_buf[slot0][n, c*32+lane]
    int tid  = threadIdx.x;
    int wid  = tid >> 5;
    int lane = tid & 31;
    int n = (blockIdx.x - SORT_BLOCKS) * 8 + wid;
    if (n >= N_NODES) return;

    const float* xp = x + ((size_t)lane * N_NODES + n) * C_IN;
    float4 v0 = __ldg((const float4*)xp);
    float4 v1 = __ldg((const float4*)(xp + 4));
    float4 v2 = __ldg((const float4*)(xp + 8));
    float4 v3 = __ldg((const float4*)(xp + 12));
    float vals[16] = {v0.x, v0.y, v0.z, v0.w, v1.x, v1.y, v1.z, v1.w,
                      v2.x, v2.y, v2.z, v2.w, v3.x, v3.y, v3.z, v3.w};
    float* dst = g_buf + (size_t)n * F;
#pragma unroll
    for (int c = 0; c < C_IN; ++c) dst[c * BT + lane] = vals[c];
}

// ---------------- SpMM step (validated; rolling buffer mod 5) ----------------
#define FMA4(A, V, U) do { \
    A.x = fmaf(V, U.x, A.x); A.y = fmaf(V, U.y, A.y); \
    A.z = fmaf(V, U.z, A.z); A.w = fmaf(V, U.w, A.w); } while (0)

__global__ void __launch_bounds__(256) spmm_kernel(int kc, int kp, int ko, int first) {
    int gw   = (blockIdx.x * 256 + threadIdx.x) >> 5;   // node = global warp id
    int lane = threadIdx.x & 31;
    if (gw >= N_NODES) return;

    const float4* __restrict__ cur = (const float4*)(g_buf + (size_t)kc * N_NODES * F);
    int s = g_rowptr[gw], e = g_rowptr[gw + 1];

    float4 a0 = make_float4(0.f, 0.f, 0.f, 0.f), a1 = a0, a2 = a0, a3 = a0;

    int i = s;
    for (; i + 2 <= e; i += 2) {
        int   c0 = __ldg(&g_colidx[i]);
        int   c1 = __ldg(&g_colidx[i + 1]);
        float v0 = __ldg(&g_vals[i]);
        float v1 = __ldg(&g_vals[i + 1]);
        const float4* p0 = cur + (size_t)c0 * 128 + lane;
        const float4* p1 = cur + (size_t)c1 * 128 + lane;
        float4 u0 = __ldg(p0),      u1 = __ldg(p0 + 32),
               u2 = __ldg(p0 + 64), u3 = __ldg(p0 + 96);
        float4 w0 = __ldg(p1),      w1 = __ldg(p1 + 32),
               w2 = __ldg(p1 + 64), w3 = __ldg(p1 + 96);
        FMA4(a0, v0, u0); FMA4(a1, v0, u1); FMA4(a2, v0, u2); FMA4(a3, v0, u3);
        FMA4(a0, v1, w0); FMA4(a1, v1, w1); FMA4(a2, v1, w2); FMA4(a3, v1, w3);
    }
    if (i < e) {
        int   c0 = __ldg(&g_colidx[i]);
        float v0 = __ldg(&g_vals[i]);
        const float4* p0 = cur + (size_t)c0 * 128 + lane;
        float4 u0 = __ldg(p0),      u1 = __ldg(p0 + 32),
               u2 = __ldg(p0 + 64), u3 = __ldg(p0 + 96);
        FMA4(a0, v0, u0); FMA4(a1, v0, u1); FMA4(a2, v0, u2); FMA4(a3, v0, u3);
    }

    size_t o = (size_t)gw * 128 + lane;
    float4* dst = (float4*)(g_buf + (size_t)ko * N_NODES * F);
    if (first) {
        dst[o] = a0; dst[o + 32] = a1; dst[o + 64] = a2; dst[o + 96] = a3;
    } else {
        const float4* __restrict__ prev = (const float4*)(g_buf + (size_t)kp * N_NODES * F);
        float4 p0 = prev[o], p1 = prev[o + 32], p2 = prev[o + 64], p3 = prev[o + 96];
        dst[o]      = make_float4(2.f * a0.x - p0.x, 2.f * a0.y - p0.y, 2.f * a0.z - p0.z, 2.f * a0.w - p0.w);
        dst[o + 32] = make_float4(2.f * a1.x - p1.x, 2.f * a1.y - p1.y, 2.f * a1.z - p1.z, 2.f * a1.w - p1.w);
        dst[o + 64] = make_float4(2.f * a2.x - p2.x, 2.f * a2.y - p2.y, 2.f * a2.z - p2.z, 2.f * a2.w - p2.w);
        dst[o + 96] = make_float4(2.f * a3.x - p3.x, 2.f * a3.y - p3.y, 2.f * a3.z - p3.z, 2.f * a3.w - p3.w);
    }
}

// ---------------- projection (R8-validated v2): slices [k0, k0+nk) -> out ----------------
__device__ __forceinline__ void ffma2(ull& d, ull a, ull b) {
    asm("fma.rn.f32x2 %0, %1, %2, %0;" : "+l"(d) : "l"(a), "l"(b));
}
__device__ __forceinline__ ull dup2(float v) {
    ull r; asm("mov.b64 %0, {%1, %1};" : "=l"(r) : "f"(v)); return r;
}
__device__ __forceinline__ ull add2(ull a, ull b) {
    ull r; asm("add.rn.f32x2 %0, %1, %2;" : "=l"(r) : "l"(a), "l"(b)); return r;
}

__global__ void __launch_bounds__(256) proj_kernel(float* __restrict__ out,
                                                   int k0, int nk, int accumulate) {
    int gw   = (blockIdx.x * 256 + threadIdx.x) >> 5;   // node = global warp id
    int lane = threadIdx.x & 31;
    if (gw >= N_NODES) return;
    int n = gw;

    int btp = lane >> 3;                    // bts btp*8 .. btp*8+7
    int cj  = lane & 7;                     // couts cj*4 .. cj*4+3

    ull acc[8][2];
#pragma unroll
    for (int i = 0; i < 8; ++i) { acc[i][0] = 0ull; acc[i][1] = 0ull; }

    for (int kk = 0; kk < nk; ++kk) {
        int k = k0 + kk;
        const float* row = g_buf + ((size_t)(k % NSLOT) * N_NODES + n) * F + btp * 8;
        const float* wk  = g_Wre + k * (C_IN * COUT) + cj * 4;
#pragma unroll 4
        for (int c = 0; c < C_IN; ++c) {
            float4 sa = __ldg((const float4*)(row + c * BT));
            float4 sb = __ldg((const float4*)(row + c * BT + 4));
            float4 w4 = __ldg((const float4*)(wk + c * COUT));   // L1-hot
            ull w0 = ((ull*)&w4)[0], w1 = ((ull*)&w4)[1];
            ull d;
            d = dup2(sa.x); ffma2(acc[0][0], d, w0); ffma2(acc[0][1], d, w1);
            d = dup2(sa.y); ffma2(acc[1][0], d, w0); ffma2(acc[1][1], d, w1);
            d = dup2(sa.z); ffma2(acc[2][0], d, w0); ffma2(acc[2][1], d, w1);
            d = dup2(sa.w); ffma2(acc[3][0], d, w0); ffma2(acc[3][1], d, w1);
            d = dup2(sb.x); ffma2(acc[4][0], d, w0); ffma2(acc[4][1], d, w1);
            d = dup2(sb.y); ffma2(acc[5][0], d, w0); ffma2(acc[5][1], d, w1);
            d = dup2(sb.z); ffma2(acc[6][0], d, w0); ffma2(acc[6][1], d, w1);
            d = dup2(sb.w); ffma2(acc[7][0], d, w0); ffma2(acc[7][1], d, w1);
        }
    }

#pragma unroll
    for (int i = 0; i < 8; ++i) {
        int bt = btp * 8 + i;
        float* op = out + ((size_t)bt * N_NODES + n) * COUT + cj * 4;
        float4 res;
        if (accumulate) {
            float4 prev = *(const float4*)op;
            ((ull*)&res)[0] = add2(acc[i][0], ((ull*)&prev)[0]);
            ((ull*)&res)[1] = add2(acc[i][1], ((ull*)&prev)[1]);
        } else {
            ((ull*)&res)[0] = acc[i][0];
            ((ull*)&res)[1] = acc[i][1];
        }
        *(float4*)op = res;
    }
}

// ---------------- launch (single stream; 5 proj passes of nk=4) ----------------
extern "C" void kernel_launch(void* const* d_in, const int* in_sizes, int n_in,
                              void* d_out, int out_size) {
    const float* x    = (const float*)d_in[0];
    const int*   erow = (const int*)  d_in[1];
    const int*   ecol = (const int*)  d_in[2];
    const float* eval = (const float*)d_in[3];
    const float* W    = (const float*)d_in[4];
    float*       out  = (float*)d_out;
    int nnz = in_sizes[1];
    if (nnz > NNZ_MAX) nnz = NNZ_MAX;

    prep_kernel       <<<1, 1024>>>(erow, W, nnz);                          // idx 0
    csr_scatter_kernel<<<(nnz + 255) / 256, 256>>>(erow, ecol, eval, nnz);  // idx 1
    sort_xpose_kernel <<<SORT_BLOCKS + XP_BLOCKS, 256>>>(x);                // idx 2

    spmm_kernel<<<WARP_BLOCKS, 256>>>(0, 0, 1, 1);                          // k=1, idx 3 <- profiled
    for (int k = 2; k < KS; ++k) {
        spmm_kernel<<<WARP_BLOCKS, 256>>>((k - 1) % NSLOT, (k - 2) % NSLOT, k % NSLOT, 0);
        // proj slices [k-4, k-1] after spmm k (liveness: slot (k-4)%5 overwritten at spmm k+1)
        if ((k & 3) == 0)   // k = 4, 8, 12, 16 -> k0 = 0, 4, 8, 12; k=4 initializes out
            proj_kernel<<<WARP_BLOCKS, 256>>>(out, k - 4, 4, k != 4);
    }
    proj_kernel<<<WARP_BLOCKS, 256>>>(out, 16, 4, 1);                       // slices 16..19
}

// round 17
// speedup vs baseline: 1.0669x; 1.0669x over previous
#include <cuda_runtime.h>
#include <stdint.h>

#define N_NODES 10242
#define NNZ_MAX 71694
#define BT      32          // B*T
#define C_IN    16
#define F       512         // C_IN * BT
#define KS      20
#define COUT    32
#define CK      (C_IN * KS)
#define NSLOT   4
#define SORT_BLOCKS 41      // 41*256 >= 10242
#define XP_BLOCKS   ((N_NODES + 7) / 8)
#define WARP_BLOCKS ((N_NODES * 32 + 255) / 256)   // 1281

typedef unsigned long long ull;

// ---------------- device scratch (no runtime allocation allowed) ----------------
__device__ float g_buf[(size_t)NSLOT * N_NODES * F];   // rolling 4-slice window (~84MB)
__device__ int   g_rowptr[N_NODES + 1];
__device__ int   g_cursor[N_NODES];
__device__ int   g_colidx[NNZ_MAX];
__device__ float g_vals[NNZ_MAX];
__device__ float g_Wre[KS * C_IN * COUT];          // [k][c][cout] = W[cout*CK + c*KS + k]  (40KB)

// ---------------- kernel A: count+scan+W-reshape (single block) ----------------
__global__ void __launch_bounds__(1024) prep_kernel(const int* __restrict__ erow,
                                                    const float* __restrict__ W,
                                                    int nnz) {
    __shared__ int scnt[N_NODES];
    __shared__ int ssum[1024];
    int t = threadIdx.x;

    for (int i = t; i < N_NODES; i += 1024) scnt[i] = 0;
    __syncthreads();
    for (int e = t; e < nnz; e += 1024) atomicAdd(&scnt[erow[e]], 1);
    __syncthreads();

    const int CH = 11;                 // 1024*11 >= 10242
    int base = t * CH;
    int s = 0;
#pragma unroll
    for (int i = 0; i < CH; ++i) {
        int idx = base + i;
        if (idx < N_NODES) s += scnt[idx];
    }
    ssum[t] = s;
    __syncthreads();
    for (int off = 1; off < 1024; off <<= 1) {
        int v = (t >= off) ? ssum[t - off] : 0;
        __syncthreads();
        ssum[t] += v;
        __syncthreads();
    }
    int run = ssum[t] - s;
#pragma unroll
    for (int i = 0; i < CH; ++i) {
        int idx = base + i;
        if (idx < N_NODES) {
            g_rowptr[idx] = run;
            g_cursor[idx] = run;
            run += scnt[idx];
        }
    }
    if (t == 0) g_rowptr[N_NODES] = nnz;

    // W reshape: g_Wre[k*512 + c*32 + cout] = W[cout*CK + c*KS + k]
    for (int i = t; i < KS * C_IN * COUT; i += 1024) {
        int k = i >> 9;
        int r = i & 511;
        int c = r >> 5;
        int cout = r & 31;
        g_Wre[i] = W[cout * CK + c * KS + k];
    }
}

// ---------------- kernel B: scatter ----------------
__global__ void csr_scatter_kernel(const int* __restrict__ erow,
                                   const int* __restrict__ ecol,
                                   const float* __restrict__ eval, int nnz) {
    int e = blockIdx.x * blockDim.x + threadIdx.x;
    if (e < nnz) {
        int r = erow[e];
        int p = atomicAdd(&g_cursor[r], 1);
        g_colidx[p] = ecol[e];
        g_vals[p]   = eval[e];
    }
}

// ---------------- kernel C: per-row sort + transpose slice 0 (split grid) ----------------
__global__ void __launch_bounds__(256) sort_xpose_kernel(const float* __restrict__ x) {
    if (blockIdx.x < SORT_BLOCKS) {
        // canonical per-row order (col asc, then val asc) -> deterministic fp sums
        int r = blockIdx.x * 256 + threadIdx.x;
        if (r >= N_NODES) return;
        int s = g_rowptr[r], e = g_rowptr[r + 1];
        for (int i = s + 1; i < e; ++i) {
            int   kc = g_colidx[i];
            float kv = g_vals[i];
            int j = i - 1;
            while (j >= s && (g_colidx[j] > kc || (g_colidx[j] == kc && g_vals[j] > kv))) {
                g_colidx[j + 1] = g_colidx[j];
                g_vals[j + 1]   = g_vals[j];
                --j;
            }
            g_colidx[j + 1] = kc;
            g_vals[j + 1]   = kv;
        }
        return;
    }
    // transpose: x[bt=lane, n, c] -> g_buf[slot0][n, c*32+lane]
    int tid  = threadIdx.x;
    int wid  = tid >> 5;
    int lane = tid & 31;
    int n = (blockIdx.x - SORT_BLOCKS) * 8 + wid;
    if (n >= N_NODES) return;

    const float* xp = x + ((size_t)lane * N_NODES + n) * C_IN;
    float4 v0 = __ldg((const float4*)xp);
    float4 v1 = __ldg((const float4*)(xp + 4));
    float4 v2 = __ldg((const float4*)(xp + 8));
    float4 v3 = __ldg((const float4*)(xp + 12));
    float vals[16] = {v0.x, v0.y, v0.z, v0.w, v1.x, v1.y, v1.z, v1.w,
                      v2.x, v2.y, v2.z, v2.w, v3.x, v3.y, v3.z, v3.w};
    float* dst = g_buf + (size_t)n * F;
#pragma unroll
    for (int c = 0; c < C_IN; ++c) dst[c * BT + lane] = vals[c];
}

// ---------------- SpMM step (validated; rolling buffer mod 4) ----------------
#define FMA4(A, V, U) do { \
    A.x = fmaf(V, U.x, A.x); A.y = fmaf(V, U.y, A.y); \
    A.z = fmaf(V, U.z, A.z); A.w = fmaf(V, U.w, A.w); } while (0)

__global__ void __launch_bounds__(256) spmm_kernel(int kc, int kp, int ko, int first) {
    int gw   = (blockIdx.x * 256 + threadIdx.x) >> 5;   // node = global warp id
    int lane = threadIdx.x & 31;
    if (gw >= N_NODES) return;

    const float4* __restrict__ cur = (const float4*)(g_buf + (size_t)kc * N_NODES * F);
    int s = g_rowptr[gw], e = g_rowptr[gw + 1];

    float4 a0 = make_float4(0.f, 0.f, 0.f, 0.f), a1 = a0, a2 = a0, a3 = a0;

    int i = s;
    for (; i + 2 <= e; i += 2) {
        int   c0 = __ldg(&g_colidx[i]);
        int   c1 = __ldg(&g_colidx[i + 1]);
        float v0 = __ldg(&g_vals[i]);
        float v1 = __ldg(&g_vals[i + 1]);
        const float4* p0 = cur + (size_t)c0 * 128 + lane;
        const float4* p1 = cur + (size_t)c1 * 128 + lane;
        float4 u0 = __ldg(p0),      u1 = __ldg(p0 + 32),
               u2 = __ldg(p0 + 64), u3 = __ldg(p0 + 96);
        float4 w0 = __ldg(p1),      w1 = __ldg(p1 + 32),
               w2 = __ldg(p1 + 64), w3 = __ldg(p1 + 96);
        FMA4(a0, v0, u0); FMA4(a1, v0, u1); FMA4(a2, v0, u2); FMA4(a3, v0, u3);
        FMA4(a0, v1, w0); FMA4(a1, v1, w1); FMA4(a2, v1, w2); FMA4(a3, v1, w3);
    }
    if (i < e) {
        int   c0 = __ldg(&g_colidx[i]);
        float v0 = __ldg(&g_vals[i]);
        const float4* p0 = cur + (size_t)c0 * 128 + lane;
        float4 u0 = __ldg(p0),      u1 = __ldg(p0 + 32),
               u2 = __ldg(p0 + 64), u3 = __ldg(p0 + 96);
        FMA4(a0, v0, u0); FMA4(a1, v0, u1); FMA4(a2, v0, u2); FMA4(a3, v0, u3);
    }

    size_t o = (size_t)gw * 128 + lane;
    float4* dst = (float4*)(g_buf + (size_t)ko * N_NODES * F);
    if (first) {
        dst[o] = a0; dst[o + 32] = a1; dst[o + 64] = a2; dst[o + 96] = a3;
    } else {
        const float4* __restrict__ prev = (const float4*)(g_buf + (size_t)kp * N_NODES * F);
        float4 p0 = prev[o], p1 = prev[o + 32], p2 = prev[o + 64], p3 = prev[o + 96];
        dst[o]      = make_float4(2.f * a0.x - p0.x, 2.f * a0.y - p0.y, 2.f * a0.z - p0.z, 2.f * a0.w - p0.w);
        dst[o + 32] = make_float4(2.f * a1.x - p1.x, 2.f * a1.y - p1.y, 2.f * a1.z - p1.z, 2.f * a1.w - p1.w);
        dst[o + 64] = make_float4(2.f * a2.x - p2.x, 2.f * a2.y - p2.y, 2.f * a2.z - p2.z, 2.f * a2.w - p2.w);
        dst[o + 96] = make_float4(2.f * a3.x - p3.x, 2.f * a3.y - p3.y, 2.f * a3.z - p3.z, 2.f * a3.w - p3.w);
    }
}

// ---------------- projection (R8-validated v2): slices [k0, k0+nk) -> out ----------------
__device__ __forceinline__ void ffma2(ull& d, ull a, ull b) {
    asm("fma.rn.f32x2 %0, %1, %2, %0;" : "+l"(d) : "l"(a), "l"(b));
}
__device__ __forceinline__ ull dup2(float v) {
    ull r; asm("mov.b64 %0, {%1, %1};" : "=l"(r) : "f"(v)); return r;
}
__device__ __forceinline__ ull add2(ull a, ull b) {
    ull r; asm("add.rn.f32x2 %0, %1, %2;" : "=l"(r) : "l"(a), "l"(b)); return r;
}

__global__ void __launch_bounds__(256) proj_kernel(float* __restrict__ out,
                                                   int k0, int nk, int accumulate) {
    int gw   = (blockIdx.x * 256 + threadIdx.x) >> 5;   // node = global warp id
    int lane = threadIdx.x & 31;
    if (gw >= N_NODES) return;
    int n = gw;

    int btp = lane >> 3;                    // bts btp*8 .. btp*8+7
    int cj  = lane & 7;                     // couts cj*4 .. cj*4+3

    ull acc[8][2];
#pragma unroll
    for (int i = 0; i < 8; ++i) { acc[i][0] = 0ull; acc[i][1] = 0ull; }

    for (int kk = 0; kk < nk; ++kk) {
        int k = k0 + kk;
        const float* row = g_buf + ((size_t)(k % NSLOT) * N_NODES + n) * F + btp * 8;
        const float* wk  = g_Wre + k * (C_IN * COUT) + cj * 4;
#pragma unroll 4
        for (int c = 0; c < C_IN; ++c) {
            float4 sa = __ldg((const float4*)(row + c * BT));
            float4 sb = __ldg((const float4*)(row + c * BT + 4));
            float4 w4 = __ldg((const float4*)(wk + c * COUT));   // L1-hot
            ull w0 = ((ull*)&w4)[0], w1 = ((ull*)&w4)[1];
            ull d;
            d = dup2(sa.x); ffma2(acc[0][0], d, w0); ffma2(acc[0][1], d, w1);
            d = dup2(sa.y); ffma2(acc[1][0], d, w0); ffma2(acc[1][1], d, w1);
            d = dup2(sa.z); ffma2(acc[2][0], d, w0); ffma2(acc[2][1], d, w1);
            d = dup2(sa.w); ffma2(acc[3][0], d, w0); ffma2(acc[3][1], d, w1);
            d = dup2(sb.x); ffma2(acc[4][0], d, w0); ffma2(acc[4][1], d, w1);
            d = dup2(sb.y); ffma2(acc[5][0], d, w0); ffma2(acc[5][1], d, w1);
            d = dup2(sb.z); ffma2(acc[6][0], d, w0); ffma2(acc[6][1], d, w1);
            d = dup2(sb.w); ffma2(acc[7][0], d, w0); ffma2(acc[7][1], d, w1);
        }
    }

#pragma unroll
    for (int i = 0; i < 8; ++i) {
        int bt = btp * 8 + i;
        float* op = out + ((size_t)bt * N_NODES + n) * COUT + cj * 4;
        float4 res;
        if (accumulate) {
            float4 prev = *(const float4*)op;
            ((ull*)&res)[0] = add2(acc[i][0], ((ull*)&prev)[0]);
            ((ull*)&res)[1] = add2(acc[i][1], ((ull*)&prev)[1]);
        } else {
            ((ull*)&res)[0] = acc[i][0];
            ((ull*)&res)[1] = acc[i][1];
        }
        *(float4*)op = res;
    }
}

// ---------------- launch (single stream; 7 proj passes: 6x nk=3 + 1x nk=2) ----------------
extern "C" void kernel_launch(void* const* d_in, const int* in_sizes, int n_in,
                              void* d_out, int out_size) {
    const float* x    = (const float*)d_in[0];
    const int*   erow = (const int*)  d_in[1];
    const int*   ecol = (const int*)  d_in[2];
    const float* eval = (const float*)d_in[3];
    const float* W    = (const float*)d_in[4];
    float*       out  = (float*)d_out;
    int nnz = in_sizes[1];
    if (nnz > NNZ_MAX) nnz = NNZ_MAX;

    prep_kernel       <<<1, 1024>>>(erow, W, nnz);                          // idx 0
    csr_scatter_kernel<<<(nnz + 255) / 256, 256>>>(erow, ecol, eval, nnz);  // idx 1
    sort_xpose_kernel <<<SORT_BLOCKS + XP_BLOCKS, 256>>>(x);                // idx 2

    spmm_kernel<<<WARP_BLOCKS, 256>>>(0, 0, 1, 1);                          // k=1, idx 3 <- profiled
    for (int k = 2; k < KS; ++k) {
        spmm_kernel<<<WARP_BLOCKS, 256>>>((k - 1) % NSLOT, (k - 2) % NSLOT, k % NSLOT, 0);
        // proj slices [k-2, k] after spmm k; k=2 initializes out (nk=3 init replaces R8's nk=1)
        if (k % 3 == 2)   // k = 2, 5, 8, 11, 14, 17
            proj_kernel<<<WARP_BLOCKS, 256>>>(out, k - 2, 3, k != 2);
    }
    proj_kernel<<<WARP_BLOCKS, 256>>>(out, 18, 2, 1);                       // slices 18..19
}